// round 1
// baseline (speedup 1.0000x reference)
#include <cuda_runtime.h>
#include <cstdint>

// Problem constants
#define N_TOK 16384   // 16 * 32 * 32 tokens
#define KCB   8192    // codebook size
#define DDIM  256     // latent dim
// z layout: (b=16, d=256, h=32, w=32) row-major.
// token n: b = n>>10, hw = n&1023 ; z element (n, d) at z[b*262144 + d*1024 + hw]

// Scratch (device globals; no allocations allowed)
__device__ float              d_se[KCB];
__device__ float              d_sz[N_TOK];
__device__ unsigned long long d_minpack[N_TOK];
__device__ double             d_loss_acc;

// ---------------------------------------------------------------------------
// Prep 1: per-token ||z||^2 (correctly rounded via double), init minpack/loss
// grid 64 x 256 threads, one thread per token, coalesced across hw
// ---------------------------------------------------------------------------
__global__ void prep_sz_kernel(const float* __restrict__ z) {
    int tok = blockIdx.x * 256 + threadIdx.x;
    int b  = tok >> 10;
    int hw = tok & 1023;
    const float* base = z + (size_t)b * (DDIM * 1024) + hw;
    double s = 0.0;
#pragma unroll 8
    for (int d = 0; d < DDIM; ++d) {
        float v = base[(size_t)d * 1024];
        s += (double)v * (double)v;
    }
    d_sz[tok] = (float)s;
    d_minpack[tok] = 0xFFFFFFFFFFFFFFFFull;
    if (tok == 0) d_loss_acc = 0.0;
}

// ---------------------------------------------------------------------------
// Prep 2: per-code ||e||^2 — one warp per codebook row
// grid 1024 x 256 threads (8 warps/block)
// ---------------------------------------------------------------------------
__global__ void prep_se_kernel(const float* __restrict__ e) {
    int warp = (blockIdx.x * blockDim.x + threadIdx.x) >> 5;
    int lane = threadIdx.x & 31;
    const float* row = e + (size_t)warp * DDIM;
    double s = 0.0;
#pragma unroll
    for (int j = 0; j < DDIM / 32; ++j) {
        float v = row[lane + 32 * j];
        s += (double)v * (double)v;
    }
#pragma unroll
    for (int off = 16; off; off >>= 1)
        s += __shfl_down_sync(0xffffffffu, s, off);
    if (lane == 0) d_se[warp] = (float)s;
}

// ---------------------------------------------------------------------------
// Fused GEMM (dot = z . e) + distance quantization + argmin epilogue
// Tile: 128 tokens x 128 codes x k-chunk 16. 256 threads, 8x8 per thread.
// Distance replicates reference fp32 rounding:
//   t1 = fl(sz + se) ; d = fl(t1 - fl(2*dot))    (no FMA contraction)
// argmin with first-index tie-break via packed (f32 bits << 32 | k) u64 min.
// ---------------------------------------------------------------------------
#define BM 128
#define BN 128
#define BK 16
#define TM 8
#define TN 8

__global__ __launch_bounds__(256, 2)
void dist_argmin_kernel(const float* __restrict__ z, const float* __restrict__ e) {
    __shared__ float As[BK][BM];
    __shared__ float Bs[BK][BN];

    const int m0 = blockIdx.y * BM;   // token tile
    const int n0 = blockIdx.x * BN;   // code tile
    const int tid = threadIdx.x;
    const int tx = tid & 15;          // code sub-tile
    const int ty = tid >> 4;          // token sub-tile

    const int b = m0 >> 10;           // BM=128 divides 1024 -> single image per tile
    const float* zbase = z + (size_t)b * (DDIM * 1024) + (m0 & 1023);
    const float* ebase = e + (size_t)n0 * DDIM;

    float acc[TM][TN];
#pragma unroll
    for (int i = 0; i < TM; ++i)
#pragma unroll
        for (int j = 0; j < TN; ++j) acc[i][j] = 0.0f;

    for (int kt = 0; kt < DDIM; kt += BK) {
        // Load A tile: As[dd][tok], coalesced across tokens
#pragma unroll
        for (int it = 0; it < 8; ++it) {
            int idx = it * 256 + tid;
            int dd  = idx >> 7;
            int tok = idx & 127;
            As[dd][tok] = zbase[(size_t)(kt + dd) * 1024 + tok];
        }
        // Load B tile: Bs[dd][kcol]
#pragma unroll
        for (int it = 0; it < 8; ++it) {
            int idx  = it * 256 + tid;
            int kcol = idx >> 4;
            int dd   = idx & 15;
            Bs[dd][kcol] = ebase[(size_t)kcol * DDIM + kt + dd];
        }
        __syncthreads();

#pragma unroll
        for (int kk = 0; kk < BK; ++kk) {
            float a[TM], bb[TN];
            const float4* ar = reinterpret_cast<const float4*>(&As[kk][ty * TM]);
            float4 a0 = ar[0], a1 = ar[1];
            a[0]=a0.x; a[1]=a0.y; a[2]=a0.z; a[3]=a0.w;
            a[4]=a1.x; a[5]=a1.y; a[6]=a1.z; a[7]=a1.w;
            const float4* br = reinterpret_cast<const float4*>(&Bs[kk][tx * TN]);
            float4 b0 = br[0], b1 = br[1];
            bb[0]=b0.x; bb[1]=b0.y; bb[2]=b0.z; bb[3]=b0.w;
            bb[4]=b1.x; bb[5]=b1.y; bb[6]=b1.z; bb[7]=b1.w;
#pragma unroll
            for (int i = 0; i < TM; ++i)
#pragma unroll
                for (int j = 0; j < TN; ++j)
                    acc[i][j] = __fmaf_rn(a[i], bb[j], acc[i][j]);
        }
        __syncthreads();
    }

    // Epilogue: quantized distance + argmin
    float sev[TN];
#pragma unroll
    for (int j = 0; j < TN; ++j) sev[j] = d_se[n0 + tx * TN + j];

#pragma unroll
    for (int i = 0; i < TM; ++i) {
        const int tokrow = m0 + ty * TM + i;
        const float szv = d_sz[tokrow];
        unsigned long long best = 0xFFFFFFFFFFFFFFFFull;
#pragma unroll
        for (int j = 0; j < TN; ++j) {
            int k = n0 + tx * TN + j;
            float t1 = __fadd_rn(szv, sev[j]);             // fl(sz + se)
            float t2 = __fmul_rn(2.0f, acc[i][j]);          // exact
            float dv = __fsub_rn(t1, t2);                   // fl(t1 - 2*dot)
            // dv ~ 256 > 0 so f32 bits are order-preserving
            unsigned long long p =
                ((unsigned long long)__float_as_uint(dv) << 32) | (unsigned)k;
            best = (p < best) ? p : best;
        }
        // reduce across the 16 tx lanes sharing this token row
#pragma unroll
        for (int off = 8; off; off >>= 1) {
            unsigned long long o = __shfl_down_sync(0xffffffffu, best, off, 16);
            best = (o < best) ? o : best;
        }
        if (tx == 0) atomicMin(&d_minpack[tokrow], best);
    }
}

// ---------------------------------------------------------------------------
// Output: gather e[idx] -> out in (b,d,h,w) layout via smem transpose;
// accumulate sum((z_q - z)^2) in double.
// One block per 32 tokens, 256 threads. grid = 512.
// ---------------------------------------------------------------------------
__global__ void output_kernel(const float* __restrict__ z,
                              const float* __restrict__ e,
                              float* __restrict__ out) {
    __shared__ float zq[32][DDIM + 1];   // +1 pad: conflict-free column reads
    __shared__ double red[256];

    const int t0  = blockIdx.x * 32;
    const int b   = t0 >> 10;
    const int hw0 = t0 & 1023;
    const size_t zoff = (size_t)b * (DDIM * 1024) + hw0;
    const int tid = threadIdx.x;

    // gather 32 codebook rows (coalesced over d)
    for (int i = 0; i < 32; ++i) {
        unsigned idx = (unsigned)(d_minpack[t0 + i] & 0xFFFFFFFFu);
        zq[i][tid] = e[(size_t)idx * DDIM + tid];
    }
    __syncthreads();

    // write transposed to out; coalesced over hw within each 32-thread group
    const int t     = tid & 31;   // token within tile
    const int dbase = tid >> 5;   // 0..7
    double ls = 0.0;
#pragma unroll 4
    for (int du = 0; du < 32; ++du) {
        int dd = du * 8 + dbase;
        size_t a = zoff + (size_t)dd * 1024 + t;
        float q  = zq[t][dd];
        float zp = z[a];
        out[a] = q;
        float df = __fsub_rn(q, zp);
        ls += (double)df * (double)df;
    }

    red[tid] = ls;
    __syncthreads();
    for (int s = 128; s; s >>= 1) {
        if (tid < s) red[tid] += red[tid + s];
        __syncthreads();
    }
    if (tid == 0) atomicAdd(&d_loss_acc, red[0]);
}

// ---------------------------------------------------------------------------
// Finalize: q_loss = 1.25 * mean((z_q - z)^2)
// ---------------------------------------------------------------------------
__global__ void finalize_kernel(float* __restrict__ out, int loss_idx) {
    out[loss_idx] = (float)(1.25 * d_loss_acc / (double)((size_t)N_TOK * DDIM));
}

// ---------------------------------------------------------------------------
extern "C" void kernel_launch(void* const* d_in, const int* in_sizes, int n_in,
                              void* d_out, int out_size) {
    (void)in_sizes; (void)n_in;
    const float* z = (const float*)d_in[0];   // 16*256*32*32 fp32
    const float* e = (const float*)d_in[1];   // 8192*256 fp32
    float* out = (float*)d_out;               // 4194304 values + 1 loss

    prep_sz_kernel<<<N_TOK / 256, 256>>>(z);
    prep_se_kernel<<<KCB / 8, 256>>>(e);

    dim3 grid(KCB / BN, N_TOK / BM);
    dist_argmin_kernel<<<grid, 256>>>(z, e);

    output_kernel<<<N_TOK / 32, 256>>>(z, e, out);
    finalize_kernel<<<1, 1>>>(out, out_size - 1);
}

// round 5
// speedup vs baseline: 3.8993x; 3.8993x over previous
#include <cuda_runtime.h>
#include <cuda_bf16.h>
#include <cstdint>

// Problem constants
#define N_TOK 16384   // 16 * 32 * 32 tokens
#define KCB   8192    // codebook size
#define DDIM  256     // latent dim
#define CAP   1024    // candidate capacity per token
#define MARGIN 4.0e-4f

// z layout: (b=16, d=256, h=32, w=32) row-major.
// token n: b = n>>10, hw = n&1023 ; z element (n, d) at z[b*262144 + d*1024 + hw]

// ---------------- scratch (device globals; no runtime allocations) ----------
__device__ float              d_se[KCB];
__device__ float              d_sz[N_TOK];
__device__ float              d_zT[(size_t)N_TOK * DDIM];          // 16 MB, token-major fp32
__device__ __nv_bfloat16      d_zbf[(size_t)N_TOK * DDIM];         //  8 MB
__device__ __nv_bfloat16      d_ebf[(size_t)KCB * DDIM];           //  4 MB
__device__ unsigned           d_maxbits[N_TOK];                    // monotone-encoded max dot
__device__ int                d_ccount[N_TOK];
__device__ int                d_cand[(size_t)N_TOK * CAP];         // 64 MB
__device__ int                d_idx[N_TOK];
__device__ double             d_loss_acc;

// monotone order-preserving float <-> uint
__device__ __forceinline__ unsigned fenc(float f) {
    unsigned u = __float_as_uint(f);
    return (u & 0x80000000u) ? ~u : (u | 0x80000000u);
}
__device__ __forceinline__ float fdec(unsigned u) {
    return (u & 0x80000000u) ? __uint_as_float(u & 0x7fffffffu)
                             : __uint_as_float(~u);
}

// ---------------------------------------------------------------------------
// Transpose z (b,d,h,w) -> zT[token][d] fp32 and zbf[token][d] bf16
// ---------------------------------------------------------------------------
__global__ void transpose_z_kernel(const float* __restrict__ z) {
    __shared__ float tile[32][33];
    const int b   = blockIdx.z;
    const int d0  = blockIdx.y * 32;
    const int hw0 = blockIdx.x * 32;
    const int tx  = threadIdx.x;   // 0..31
    const int ty  = threadIdx.y;   // 0..7

#pragma unroll
    for (int i = 0; i < 4; ++i) {
        int dl = ty + i * 8;
        tile[dl][tx] = z[(size_t)b * (DDIM * 1024) + (size_t)(d0 + dl) * 1024 + hw0 + tx];
    }
    __syncthreads();
#pragma unroll
    for (int i = 0; i < 4; ++i) {
        int hl  = ty + i * 8;
        int tok = b * 1024 + hw0 + hl;
        float v = tile[tx][hl];
        d_zT[(size_t)tok * DDIM + d0 + tx]  = v;
        d_zbf[(size_t)tok * DDIM + d0 + tx] = __float2bfloat16(v);
    }
}

// ---------------------------------------------------------------------------
// Per-token ||z||^2 (double), init maxbits/ccount/loss.  warp per token.
// ---------------------------------------------------------------------------
__global__ void prep_tok_kernel() {
    int tok  = blockIdx.x * 8 + (threadIdx.x >> 5);
    int lane = threadIdx.x & 31;
    const float* row = &d_zT[(size_t)tok * DDIM];
    double s = 0.0;
#pragma unroll
    for (int j = 0; j < DDIM / 32; ++j) {
        float v = row[lane + 32 * j];
        s += (double)v * (double)v;
    }
#pragma unroll
    for (int off = 16; off; off >>= 1)
        s += __shfl_down_sync(0xffffffffu, s, off);
    if (lane == 0) {
        d_sz[tok]      = (float)s;
        d_maxbits[tok] = 0u;
        d_ccount[tok]  = 0;
        if (tok == 0) d_loss_acc = 0.0;
    }
}

// ---------------------------------------------------------------------------
// Per-code ||e||^2 + bf16 conversion. warp per code row.
// ---------------------------------------------------------------------------
__global__ void prep_se_kernel(const float* __restrict__ e) {
    int warp = (blockIdx.x * blockDim.x + threadIdx.x) >> 5;
    int lane = threadIdx.x & 31;
    const float* row = e + (size_t)warp * DDIM;
    double s = 0.0;
#pragma unroll
    for (int j = 0; j < DDIM / 32; ++j) {
        float v = row[lane + 32 * j];
        s += (double)v * (double)v;
        d_ebf[(size_t)warp * DDIM + lane + 32 * j] = __float2bfloat16(v);
    }
#pragma unroll
    for (int off = 16; off; off >>= 1)
        s += __shfl_down_sync(0xffffffffu, s, off);
    if (lane == 0) d_se[warp] = (float)s;
}

// ---------------------------------------------------------------------------
// Pass 1: bf16 mma.sync GEMM (dot = z.e) + running-max + candidate append
// Block 128x128, BK=32, 8 warps (2 m x 4 n), warp tile 64x32.
// ---------------------------------------------------------------------------
#define P1_LD 40   // padded row length in bf16 (80B -> conflict-free ldmatrix)

__device__ __forceinline__ void ldm_x4(uint32_t* r, const __nv_bfloat16* p) {
    unsigned a = (unsigned)__cvta_generic_to_shared(p);
    asm volatile("ldmatrix.sync.aligned.m8n8.x4.shared.b16 {%0,%1,%2,%3}, [%4];"
                 : "=r"(r[0]), "=r"(r[1]), "=r"(r[2]), "=r"(r[3]) : "r"(a));
}
__device__ __forceinline__ void mma_bf16(float* c, const uint32_t* a, const uint32_t* b) {
    asm volatile(
        "mma.sync.aligned.m16n8k16.row.col.f32.bf16.bf16.f32 "
        "{%0,%1,%2,%3},{%4,%5,%6,%7},{%8,%9},{%0,%1,%2,%3};"
        : "+f"(c[0]), "+f"(c[1]), "+f"(c[2]), "+f"(c[3])
        : "r"(a[0]), "r"(a[1]), "r"(a[2]), "r"(a[3]), "r"(b[0]), "r"(b[1]));
}

__global__ __launch_bounds__(256)
void pass1_kernel() {
    __shared__ __nv_bfloat16 As[128 * P1_LD];
    __shared__ __nv_bfloat16 Bs[128 * P1_LD];

    const int tid  = threadIdx.x;
    const int lane = tid & 31;
    const int warp = tid >> 5;
    const int wm   = warp & 1;    // 0..1
    const int wn   = warp >> 1;   // 0..3
    const int m0   = blockIdx.y * 128;
    const int n0   = blockIdx.x * 128;

    // ldmatrix lane addressing constants
    const int a_row  = (lane & 7) + ((lane >> 3) & 1) * 8;   // 0..15
    const int a_colo = (lane >> 4) * 8;                      // 0 or 8
    // B (smem [n][k] == col-major KxN): NON-trans ldmatrix.
    // lanes 0-7: n0-7/k0 | 8-15: n0-7/k8 | 16-23: n8-15/k0 | 24-31: n8-15/k8
    // -> r0=(n0-7,k0-7) r1=(n0-7,k8-15) r2=(n8-15,k0-7) r3=(n8-15,k8-15)
    const int b_rowo = ((lane >> 4) & 1) * 8 + (lane & 7);
    const int b_colo = ((lane >> 3) & 1) * 8;

    float acc[4][4][4];
#pragma unroll
    for (int i = 0; i < 4; ++i)
#pragma unroll
        for (int j = 0; j < 4; ++j)
#pragma unroll
            for (int q = 0; q < 4; ++q) acc[i][j][q] = 0.0f;

    for (int kt = 0; kt < DDIM; kt += 32) {
        __syncthreads();
#pragma unroll
        for (int it = 0; it < 2; ++it) {
            int v   = tid + it * 256;
            int row = v >> 2, seg = v & 3;
            *reinterpret_cast<uint4*>(&As[row * P1_LD + seg * 8]) =
                *reinterpret_cast<const uint4*>(&d_zbf[(size_t)(m0 + row) * DDIM + kt + seg * 8]);
            *reinterpret_cast<uint4*>(&Bs[row * P1_LD + seg * 8]) =
                *reinterpret_cast<const uint4*>(&d_ebf[(size_t)(n0 + row) * DDIM + kt + seg * 8]);
        }
        __syncthreads();

#pragma unroll
        for (int ks = 0; ks < 32; ks += 16) {
            uint32_t afr[4][4];
#pragma unroll
            for (int mi = 0; mi < 4; ++mi)
                ldm_x4(afr[mi], &As[(wm * 64 + mi * 16 + a_row) * P1_LD + ks + a_colo]);
            uint32_t bfr[2][4];  // each x4 covers two n8 tiles: {r0,r1}, {r2,r3}
#pragma unroll
            for (int bp = 0; bp < 2; ++bp)
                ldm_x4(bfr[bp], &Bs[(wn * 32 + bp * 16 + b_rowo) * P1_LD + ks + b_colo]);
#pragma unroll
            for (int mi = 0; mi < 4; ++mi)
#pragma unroll
                for (int ni = 0; ni < 4; ++ni)
                    mma_bf16(acc[mi][ni], afr[mi], &bfr[ni >> 1][(ni & 1) * 2]);
        }
    }

    // Epilogue: per-token running max + candidate append
    const int g = lane >> 2, t = lane & 3;
#pragma unroll
    for (int mi = 0; mi < 4; ++mi) {
#pragma unroll
        for (int h = 0; h < 2; ++h) {
            const int row = m0 + wm * 64 + mi * 16 + h * 8 + g;
            float vals[8];
            float rmax = -3.0e38f;
#pragma unroll
            for (int ni = 0; ni < 4; ++ni) {
                vals[2 * ni]     = acc[mi][ni][h * 2];
                vals[2 * ni + 1] = acc[mi][ni][h * 2 + 1];
                rmax = fmaxf(rmax, fmaxf(vals[2 * ni], vals[2 * ni + 1]));
            }
#pragma unroll
            for (int off = 1; off < 4; off <<= 1)
                rmax = fmaxf(rmax, __shfl_xor_sync(0xffffffffu, rmax, off));
            float thr = 0.0f;
            if (t == 0) {
                unsigned old = atomicMax(&d_maxbits[row], fenc(rmax));
                thr = fmaxf(rmax, fdec(old)) - MARGIN;   // fdec(0)=NaN ignored by fmaxf
            }
            thr = __shfl_sync(0xffffffffu, thr, lane & ~3);
#pragma unroll
            for (int ni = 0; ni < 4; ++ni) {
#pragma unroll
                for (int j = 0; j < 2; ++j) {
                    if (vals[2 * ni + j] >= thr) {
                        int pos = atomicAdd(&d_ccount[row], 1);
                        if (pos < CAP)
                            d_cand[(size_t)row * CAP + pos] =
                                n0 + wn * 32 + ni * 8 + 2 * t + j;
                    }
                }
            }
        }
    }
}

// ---------------------------------------------------------------------------
// Pass 2: exact fp32 re-rank of candidates. warp per token.
// d = fl(fl(sz+se) - fl(2*dot)); argmin with lowest-index tie-break.
// ---------------------------------------------------------------------------
__global__ void rerank_kernel(const float* __restrict__ e) {
    const int tok  = blockIdx.x * 8 + (threadIdx.x >> 5);
    const int lane = threadIdx.x & 31;

    float zr[8];
#pragma unroll
    for (int j = 0; j < 8; ++j)
        zr[j] = d_zT[(size_t)tok * DDIM + j * 32 + lane];

    const float szv = d_sz[tok];
    int cnt = d_ccount[tok];
    bool fallback = (cnt > CAP);
    int n_c = fallback ? KCB : cnt;

    unsigned long long best = 0xFFFFFFFFFFFFFFFFull;
    for (int i = 0; i < n_c; ++i) {
        int k = fallback ? i : d_cand[(size_t)tok * CAP + i];
        const float* er = e + (size_t)k * DDIM;
        float dot = 0.0f;
#pragma unroll
        for (int j = 0; j < 8; ++j)
            dot = __fmaf_rn(zr[j], er[j * 32 + lane], dot);
#pragma unroll
        for (int off = 16; off; off >>= 1)
            dot += __shfl_down_sync(0xffffffffu, dot, off);
        if (lane == 0) {
            float t1 = __fadd_rn(szv, d_se[k]);
            float t2 = __fmul_rn(2.0f, dot);
            float dv = __fsub_rn(t1, t2);
            unsigned long long p =
                ((unsigned long long)__float_as_uint(dv) << 32) | (unsigned)k;
            best = (p < best) ? p : best;
        }
    }
    if (lane == 0) d_idx[tok] = (int)(unsigned)(best & 0xFFFFFFFFu);
}

// ---------------------------------------------------------------------------
// Output: gather e[idx] -> out in (b,d,h,w) layout; accumulate loss (double).
// ---------------------------------------------------------------------------
__global__ void output_kernel(const float* __restrict__ z,
                              const float* __restrict__ e,
                              float* __restrict__ out) {
    __shared__ float zq[32][DDIM + 1];
    __shared__ double red[256];

    const int t0  = blockIdx.x * 32;
    const int b   = t0 >> 10;
    const int hw0 = t0 & 1023;
    const size_t zoff = (size_t)b * (DDIM * 1024) + hw0;
    const int tid = threadIdx.x;

    for (int i = 0; i < 32; ++i) {
        unsigned idx = (unsigned)d_idx[t0 + i];
        zq[i][tid] = e[(size_t)idx * DDIM + tid];
    }
    __syncthreads();

    const int t     = tid & 31;
    const int dbase = tid >> 5;
    double ls = 0.0;
#pragma unroll 4
    for (int du = 0; du < 32; ++du) {
        int dd = du * 8 + dbase;
        size_t a = zoff + (size_t)dd * 1024 + t;
        float q  = zq[t][dd];
        float zp = z[a];
        out[a] = q;
        float df = __fsub_rn(q, zp);
        ls += (double)df * (double)df;
    }

    red[tid] = ls;
    __syncthreads();
    for (int s = 128; s; s >>= 1) {
        if (tid < s) red[tid] += red[tid + s];
        __syncthreads();
    }
    if (tid == 0) atomicAdd(&d_loss_acc, red[0]);
}

__global__ void finalize_kernel(float* __restrict__ out, int loss_idx) {
    out[loss_idx] = (float)(1.25 * d_loss_acc / (double)((size_t)N_TOK * DDIM));
}

// ---------------------------------------------------------------------------
extern "C" void kernel_launch(void* const* d_in, const int* in_sizes, int n_in,
                              void* d_out, int out_size) {
    (void)in_sizes; (void)n_in;
    const float* z = (const float*)d_in[0];
    const float* e = (const float*)d_in[1];
    float* out = (float*)d_out;

    dim3 tgrid(32, 8, 16), tblk(32, 8);
    transpose_z_kernel<<<tgrid, tblk>>>(z);
    prep_tok_kernel<<<N_TOK / 8, 256>>>();
    prep_se_kernel<<<KCB / 8, 256>>>(e);

    dim3 g1(KCB / 128, N_TOK / 128);
    pass1_kernel<<<g1, 256>>>();

    rerank_kernel<<<N_TOK / 8, 256>>>(e);
    output_kernel<<<N_TOK / 32, 256>>>(z, e, out);
    finalize_kernel<<<1, 1>>>(out, out_size - 1);
}

// round 9
// speedup vs baseline: 4.8006x; 1.2311x over previous
#include <cuda_runtime.h>
#include <cuda_bf16.h>
#include <cstdint>

// Problem constants
#define N_TOK 16384   // 16 * 32 * 32 tokens
#define KCB   8192    // codebook size
#define DDIM  256     // latent dim
#define CAP   1024    // candidate capacity per token
#define MARGIN 4.0e-4f

// z layout: (b=16, d=256, h=32, w=32) row-major.
// token n: b = n>>10, hw = n&1023 ; z element (n, d) at z[b*262144 + d*1024 + hw]

// ---------------- scratch (device globals; no runtime allocations) ----------
__device__ float              d_se[KCB];
__device__ float              d_sz[N_TOK];
__device__ float              d_zT[(size_t)N_TOK * DDIM];          // 16 MB token-major fp32
__device__ __nv_bfloat16      d_zbf[(size_t)N_TOK * DDIM];         //  8 MB
__device__ __nv_bfloat16      d_ebf[(size_t)KCB * DDIM];           //  4 MB
__device__ unsigned           d_maxbits[N_TOK];                    // monotone-encoded max dot
__device__ int                d_ccount[N_TOK];
__device__ int                d_cand[(size_t)N_TOK * CAP];         // 64 MB
__device__ int                d_idx[N_TOK];
__device__ double             d_loss_acc;

// monotone order-preserving float <-> uint
__device__ __forceinline__ unsigned fenc(float f) {
    unsigned u = __float_as_uint(f);
    return (u & 0x80000000u) ? ~u : (u | 0x80000000u);
}
__device__ __forceinline__ float fdec(unsigned u) {
    return (u & 0x80000000u) ? __uint_as_float(u & 0x7fffffffu)
                             : __uint_as_float(~u);
}

// ---------------------------------------------------------------------------
// cp.async helpers
// ---------------------------------------------------------------------------
#define CP_ASYNC16(dst_u32, src_ptr) \
    asm volatile("cp.async.cg.shared.global [%0], [%1], 16;" \
                 :: "r"(dst_u32), "l"(src_ptr))
#define CP_COMMIT() asm volatile("cp.async.commit_group;")
#define CP_WAIT(n)  asm volatile("cp.async.wait_group %0;" :: "n"(n))

// ---------------------------------------------------------------------------
// Transpose z (b,d,h,w) -> zT[token][d] fp32 and zbf[token][d] bf16
// ---------------------------------------------------------------------------
__global__ void transpose_z_kernel(const float* __restrict__ z) {
    __shared__ float tile[32][33];
    const int b   = blockIdx.z;
    const int d0  = blockIdx.y * 32;
    const int hw0 = blockIdx.x * 32;
    const int tx  = threadIdx.x;   // 0..31
    const int ty  = threadIdx.y;   // 0..7

#pragma unroll
    for (int i = 0; i < 4; ++i) {
        int dl = ty + i * 8;
        tile[dl][tx] = z[(size_t)b * (DDIM * 1024) + (size_t)(d0 + dl) * 1024 + hw0 + tx];
    }
    __syncthreads();
#pragma unroll
    for (int i = 0; i < 4; ++i) {
        int hl  = ty + i * 8;
        int tok = b * 1024 + hw0 + hl;
        float v = tile[tx][hl];
        d_zT[(size_t)tok * DDIM + d0 + tx]  = v;
        d_zbf[(size_t)tok * DDIM + d0 + tx] = __float2bfloat16(v);
    }
}

// ---------------------------------------------------------------------------
// Per-token ||z||^2 (double), init maxbits/ccount/loss.  warp per token.
// ---------------------------------------------------------------------------
__global__ void prep_tok_kernel() {
    int tok  = blockIdx.x * 8 + (threadIdx.x >> 5);
    int lane = threadIdx.x & 31;
    const float* row = &d_zT[(size_t)tok * DDIM];
    double s = 0.0;
#pragma unroll
    for (int j = 0; j < DDIM / 32; ++j) {
        float v = row[lane + 32 * j];
        s += (double)v * (double)v;
    }
#pragma unroll
    for (int off = 16; off; off >>= 1)
        s += __shfl_down_sync(0xffffffffu, s, off);
    if (lane == 0) {
        d_sz[tok]      = (float)s;
        d_maxbits[tok] = 0u;
        d_ccount[tok]  = 0;
        if (tok == 0) d_loss_acc = 0.0;
    }
}

// ---------------------------------------------------------------------------
// Per-code ||e||^2 + bf16 conversion. warp per code row.
// ---------------------------------------------------------------------------
__global__ void prep_se_kernel(const float* __restrict__ e) {
    int warp = (blockIdx.x * blockDim.x + threadIdx.x) >> 5;
    int lane = threadIdx.x & 31;
    const float* row = e + (size_t)warp * DDIM;
    double s = 0.0;
#pragma unroll
    for (int j = 0; j < DDIM / 32; ++j) {
        float v = row[lane + 32 * j];
        s += (double)v * (double)v;
        d_ebf[(size_t)warp * DDIM + lane + 32 * j] = __float2bfloat16(v);
    }
#pragma unroll
    for (int off = 16; off; off >>= 1)
        s += __shfl_down_sync(0xffffffffu, s, off);
    if (lane == 0) d_se[warp] = (float)s;
}

// ---------------------------------------------------------------------------
// Pass 1: bf16 mma.sync GEMM (dot = z.e) + running-max + candidate append.
// Block 128x128, BK=64, cp.async double-buffered. 8 warps (2m x 4n), warp 64x32.
// smem: row pad 72 els (144B): 8-row ldmatrix footprint spans 128B of bank
// space (144 mod 128 = 16) -> conflict-free; 16B aligned for cp.async.
// ---------------------------------------------------------------------------
#define P1_LD   72                 // padded row length (elements)
#define P1_ABYTES (128 * P1_LD * 2)  // 18432 per buffer
#define P1_SMEM   (4 * P1_ABYTES)    // Abuf0, Abuf1, Bbuf0, Bbuf1 = 73728

__device__ __forceinline__ void ldm_x4(uint32_t* r, const __nv_bfloat16* p) {
    unsigned a = (unsigned)__cvta_generic_to_shared(p);
    asm volatile("ldmatrix.sync.aligned.m8n8.x4.shared.b16 {%0,%1,%2,%3}, [%4];"
                 : "=r"(r[0]), "=r"(r[1]), "=r"(r[2]), "=r"(r[3]) : "r"(a));
}
__device__ __forceinline__ void mma_bf16(float* c, const uint32_t* a, const uint32_t* b) {
    asm volatile(
        "mma.sync.aligned.m16n8k16.row.col.f32.bf16.bf16.f32 "
        "{%0,%1,%2,%3},{%4,%5,%6,%7},{%8,%9},{%0,%1,%2,%3};"
        : "+f"(c[0]), "+f"(c[1]), "+f"(c[2]), "+f"(c[3])
        : "r"(a[0]), "r"(a[1]), "r"(a[2]), "r"(a[3]), "r"(b[0]), "r"(b[1]));
}

// Issue cp.async for K-stage s (64 k-values) into buffer s&1.
__device__ __forceinline__ void p1_load_stage(char* smem, int s, int m0, int n0, int tid) {
    const int buf = s & 1;
    const int kt  = s * 64;
    __nv_bfloat16* As = (__nv_bfloat16*)(smem + buf * P1_ABYTES);
    __nv_bfloat16* Bs = (__nv_bfloat16*)(smem + (2 + buf) * P1_ABYTES);
    // Each tile: 128 rows x 64 els = 128 rows x 8 segs of 16B = 1024 chunks.
    // 256 threads -> 4 chunks each per tile.
#pragma unroll
    for (int it = 0; it < 4; ++it) {
        int id  = it * 256 + tid;
        int row = id >> 3, seg = id & 7;
        unsigned dstA = (unsigned)__cvta_generic_to_shared(&As[row * P1_LD + seg * 8]);
        CP_ASYNC16(dstA, (const void*)&d_zbf[(size_t)(m0 + row) * DDIM + kt + seg * 8]);
        unsigned dstB = (unsigned)__cvta_generic_to_shared(&Bs[row * P1_LD + seg * 8]);
        CP_ASYNC16(dstB, (const void*)&d_ebf[(size_t)(n0 + row) * DDIM + kt + seg * 8]);
    }
    CP_COMMIT();
}

__global__ __launch_bounds__(256, 2)
void pass1_kernel() {
    extern __shared__ char smem[];

    const int tid  = threadIdx.x;
    const int lane = tid & 31;
    const int warp = tid >> 5;
    const int wm   = warp & 1;    // 0..1
    const int wn   = warp >> 1;   // 0..3
    const int m0   = blockIdx.y * 128;
    const int n0   = blockIdx.x * 128;

    // ldmatrix lane addressing constants
    const int a_row  = (lane & 7) + ((lane >> 3) & 1) * 8;   // 0..15
    const int a_colo = (lane >> 4) * 8;                      // 0 or 8
    // B (smem [n][k] == col-major KxN): NON-trans ldmatrix (validated round 5).
    const int b_rowo = ((lane >> 4) & 1) * 8 + (lane & 7);
    const int b_colo = ((lane >> 3) & 1) * 8;

    float acc[4][4][4];
#pragma unroll
    for (int i = 0; i < 4; ++i)
#pragma unroll
        for (int j = 0; j < 4; ++j)
#pragma unroll
            for (int q = 0; q < 4; ++q) acc[i][j][q] = 0.0f;

    // --- pipelined mainloop: 4 stages of BK=64, double-buffered ---
    p1_load_stage(smem, 0, m0, n0, tid);

#pragma unroll
    for (int s = 0; s < 4; ++s) {
        if (s + 1 < 4) p1_load_stage(smem, s + 1, m0, n0, tid);
        if (s + 1 < 4) { CP_WAIT(1); } else { CP_WAIT(0); }
        __syncthreads();

        const __nv_bfloat16* As =
            (const __nv_bfloat16*)(smem + (s & 1) * P1_ABYTES);
        const __nv_bfloat16* Bs =
            (const __nv_bfloat16*)(smem + (2 + (s & 1)) * P1_ABYTES);

#pragma unroll
        for (int ks = 0; ks < 64; ks += 16) {
            uint32_t afr[4][4];
#pragma unroll
            for (int mi = 0; mi < 4; ++mi)
                ldm_x4(afr[mi], &As[(wm * 64 + mi * 16 + a_row) * P1_LD + ks + a_colo]);
            uint32_t bfr[2][4];  // each x4 covers two n8 tiles: {r0,r1},{r2,r3}
#pragma unroll
            for (int bp = 0; bp < 2; ++bp)
                ldm_x4(bfr[bp], &Bs[(wn * 32 + bp * 16 + b_rowo) * P1_LD + ks + b_colo]);
#pragma unroll
            for (int mi = 0; mi < 4; ++mi)
#pragma unroll
                for (int ni = 0; ni < 4; ++ni)
                    mma_bf16(acc[mi][ni], afr[mi], &bfr[ni >> 1][(ni & 1) * 2]);
        }
        __syncthreads();   // buffer s&1 free for stage s+2's cp.async
    }

    // Epilogue: per-token running max + candidate append
    const int g = lane >> 2, t = lane & 3;
#pragma unroll
    for (int mi = 0; mi < 4; ++mi) {
#pragma unroll
        for (int h = 0; h < 2; ++h) {
            const int row = m0 + wm * 64 + mi * 16 + h * 8 + g;
            float vals[8];
            float rmax = -3.0e38f;
#pragma unroll
            for (int ni = 0; ni < 4; ++ni) {
                vals[2 * ni]     = acc[mi][ni][h * 2];
                vals[2 * ni + 1] = acc[mi][ni][h * 2 + 1];
                rmax = fmaxf(rmax, fmaxf(vals[2 * ni], vals[2 * ni + 1]));
            }
#pragma unroll
            for (int off = 1; off < 4; off <<= 1)
                rmax = fmaxf(rmax, __shfl_xor_sync(0xffffffffu, rmax, off));
            float thr = 0.0f;
            if (t == 0) {
                unsigned old = atomicMax(&d_maxbits[row], fenc(rmax));
                thr = fmaxf(rmax, fdec(old)) - MARGIN;   // fdec(0)=NaN ignored by fmaxf
            }
            thr = __shfl_sync(0xffffffffu, thr, lane & ~3);
#pragma unroll
            for (int ni = 0; ni < 4; ++ni) {
#pragma unroll
                for (int j = 0; j < 2; ++j) {
                    if (vals[2 * ni + j] >= thr) {
                        int pos = atomicAdd(&d_ccount[row], 1);
                        if (pos < CAP)
                            d_cand[(size_t)row * CAP + pos] =
                                n0 + wn * 32 + ni * 8 + 2 * t + j;
                    }
                }
            }
        }
    }
}

// ---------------------------------------------------------------------------
// Pass 2: exact fp32 re-rank of candidates. warp per token.
// d = fl(fl(sz+se) - fl(2*dot)); argmin with lowest-index tie-break.
// ---------------------------------------------------------------------------
__global__ void rerank_kernel(const float* __restrict__ e) {
    const int tok  = blockIdx.x * 8 + (threadIdx.x >> 5);
    const int lane = threadIdx.x & 31;

    float zr[8];
#pragma unroll
    for (int j = 0; j < 8; ++j)
        zr[j] = d_zT[(size_t)tok * DDIM + j * 32 + lane];

    const float szv = d_sz[tok];
    int cnt = d_ccount[tok];
    bool fallback = (cnt > CAP);
    int n_c = fallback ? KCB : cnt;

    unsigned long long best = 0xFFFFFFFFFFFFFFFFull;
    for (int i = 0; i < n_c; ++i) {
        int k = fallback ? i : d_cand[(size_t)tok * CAP + i];
        const float* er = e + (size_t)k * DDIM;
        float dot = 0.0f;
#pragma unroll
        for (int j = 0; j < 8; ++j)
            dot = __fmaf_rn(zr[j], er[j * 32 + lane], dot);
#pragma unroll
        for (int off = 16; off; off >>= 1)
            dot += __shfl_down_sync(0xffffffffu, dot, off);
        if (lane == 0) {
            float t1 = __fadd_rn(szv, d_se[k]);
            float t2 = __fmul_rn(2.0f, dot);
            float dv = __fsub_rn(t1, t2);
            unsigned long long p =
                ((unsigned long long)__float_as_uint(dv) << 32) | (unsigned)k;
            best = (p < best) ? p : best;
        }
    }
    if (lane == 0) d_idx[tok] = (int)(unsigned)(best & 0xFFFFFFFFu);
}

// ---------------------------------------------------------------------------
// Output: gather e[idx] -> out in (b,d,h,w) layout; accumulate loss (double).
// ---------------------------------------------------------------------------
__global__ void output_kernel(const float* __restrict__ z,
                              const float* __restrict__ e,
                              float* __restrict__ out) {
    __shared__ float zq[32][DDIM + 1];
    __shared__ double red[256];

    const int t0  = blockIdx.x * 32;
    const int b   = t0 >> 10;
    const int hw0 = t0 & 1023;
    const size_t zoff = (size_t)b * (DDIM * 1024) + hw0;
    const int tid = threadIdx.x;

    for (int i = 0; i < 32; ++i) {
        unsigned idx = (unsigned)d_idx[t0 + i];
        zq[i][tid] = e[(size_t)idx * DDIM + tid];
    }
    __syncthreads();

    const int t     = tid & 31;
    const int dbase = tid >> 5;
    double ls = 0.0;
#pragma unroll 4
    for (int du = 0; du < 32; ++du) {
        int dd = du * 8 + dbase;
        size_t a = zoff + (size_t)dd * 1024 + t;
        float q  = zq[t][dd];
        float zp = z[a];
        out[a] = q;
        float df = __fsub_rn(q, zp);
        ls += (double)df * (double)df;
    }

    red[tid] = ls;
    __syncthreads();
    for (int s = 128; s; s >>= 1) {
        if (tid < s) red[tid] += red[tid + s];
        __syncthreads();
    }
    if (tid == 0) atomicAdd(&d_loss_acc, red[0]);
}

__global__ void finalize_kernel(float* __restrict__ out, int loss_idx) {
    out[loss_idx] = (float)(1.25 * d_loss_acc / (double)((size_t)N_TOK * DDIM));
}

// ---------------------------------------------------------------------------
extern "C" void kernel_launch(void* const* d_in, const int* in_sizes, int n_in,
                              void* d_out, int out_size) {
    (void)in_sizes; (void)n_in;
    const float* z = (const float*)d_in[0];
    const float* e = (const float*)d_in[1];
    float* out = (float*)d_out;

    static int smem_set = 0;
    if (!smem_set) {
        cudaFuncSetAttribute(pass1_kernel,
                             cudaFuncAttributeMaxDynamicSharedMemorySize, P1_SMEM);
        smem_set = 1;
    }

    dim3 tgrid(32, 8, 16), tblk(32, 8);
    transpose_z_kernel<<<tgrid, tblk>>>(z);
    prep_tok_kernel<<<N_TOK / 8, 256>>>();
    prep_se_kernel<<<KCB / 8, 256>>>(e);

    dim3 g1(KCB / 128, N_TOK / 128);
    pass1_kernel<<<g1, 256, P1_SMEM>>>();

    rerank_kernel<<<N_TOK / 8, 256>>>(e);
    output_kernel<<<N_TOK / 32, 256>>>(z, e, out);
    finalize_kernel<<<1, 1>>>(out, out_size - 1);
}